// round 8
// baseline (speedup 1.0000x reference)
#include <cuda_runtime.h>
#include <cuda_fp16.h>
#include <cstdint>

// LSTM B=8192, T=128, I=32, H=64, OUT=8.
// R8: R7 (fp16 m16n8k16, frag-major LDS.128, interleaved 2-group pipeline)
// + f16x2 tanh for the i/f/o sigmoids (g and tanh(c) stay fp32).

#define B_TOT 8192
#define T_LEN 128
#define I_SZ  32
#define H_SZ  64
#define OUT_SZ 8
#define M_BLK 64
#define NTHREADS 256

__device__ __forceinline__ uint32_t packh2(float a, float b) {
    __half2 h = __floats2half2_rn(a, b);
    return *reinterpret_cast<uint32_t*>(&h);
}
__device__ __forceinline__ float tanhhw(float x) {
    float y;
    asm("tanh.approx.f32 %0, %1;" : "=f"(y) : "f"(x));
    return y;
}
// two tanh in one MUFU op via f16x2
__device__ __forceinline__ float2 tanh2(float a, float b) {
    __half2 hin = __floats2half2_rn(a, b);
    uint32_t u = *reinterpret_cast<uint32_t*>(&hin);
    uint32_t v;
    asm("tanh.approx.f16x2 %0, %1;" : "=r"(v) : "r"(u));
    __half2 hout = *reinterpret_cast<__half2*>(&v);
    return __half22float2(hout);
}
__device__ __forceinline__ void mma_f16(float c[4],
                                        uint32_t a0, uint32_t a1, uint32_t a2, uint32_t a3,
                                        uint32_t b0, uint32_t b1) {
    asm("mma.sync.aligned.m16n8k16.row.col.f32.f16.f16.f32 "
        "{%0,%1,%2,%3},{%4,%5,%6,%7},{%8,%9},{%0,%1,%2,%3};"
        : "+f"(c[0]), "+f"(c[1]), "+f"(c[2]), "+f"(c[3])
        : "r"(a0), "r"(a1), "r"(a2), "r"(a3), "r"(b0), "r"(b1));
}

// one (q, r) fragment: LDS.128 + 4 gate MMAs
__device__ __forceinline__ void frag_mma(float accr[4][4], const uint32_t* __restrict__ blk,
                                         int lane, const uint32_t (&bfr)[4][6][2], int q) {
    uint4 av = *reinterpret_cast<const uint4*>(blk + lane * 4);
    #pragma unroll
    for (int g = 0; g < 4; ++g)
        mma_f16(accr[g], av.x, av.y, av.z, av.w, bfr[g][q][0], bfr[g][q][1]);
}

// activate 4 elems; i/f/o accs pre-scaled by 0.5 (sigmoid = 0.5*tanh+0.5)
// i/f/o tanh in f16x2 (6 MUFU), g + tanh(c) in fp32 (8 MUFU)
__device__ __forceinline__ void act_r(const float acc[4][4], float cst[4], float hv[4]) {
    float2 i01 = tanh2(acc[0][0], acc[0][1]);
    float2 i23 = tanh2(acc[0][2], acc[0][3]);
    float2 f01 = tanh2(acc[1][0], acc[1][1]);
    float2 f23 = tanh2(acc[1][2], acc[1][3]);
    float2 o01 = tanh2(acc[3][0], acc[3][1]);
    float2 o23 = tanh2(acc[3][2], acc[3][3]);
    const float ig[4] = {i01.x, i01.y, i23.x, i23.y};
    const float fg[4] = {f01.x, f01.y, f23.x, f23.y};
    const float og[4] = {o01.x, o01.y, o23.x, o23.y};
    #pragma unroll
    for (int e = 0; e < 4; ++e) {
        float i = fmaf(ig[e], 0.5f, 0.5f);
        float f = fmaf(fg[e], 0.5f, 0.5f);
        float g = tanhhw(acc[2][e]);
        float o = fmaf(og[e], 0.5f, 0.5f);
        float c = f * cst[e] + i * g;
        cst[e] = c;
        hv[e] = o * tanhhw(c);
    }
}

// Phase: mma(group GM) into accM; act(accA -> h of group GA); stage x(GA,t+1).
template <int GM, int GA>
__device__ __forceinline__ void phase_fn(uint32_t* __restrict__ Xs, uint32_t* __restrict__ Hs,
                                         float (&accM)[2][4][4], float (&accA)[2][4][4],
                                         float (&cst)[2][4], float4& xr,
                                         const float* __restrict__ xga, int t, int lane,
                                         int xoff0, int xoff1, int hoff0, int hoff1,
                                         const uint32_t (&bfr)[4][6][2],
                                         const float (&bias2)[4][2]) {
    const uint32_t* Xm = Xs + GM * 512;
    const uint32_t* Hm = Hs + GM * 1024;

    #pragma unroll
    for (int r = 0; r < 2; ++r)
        #pragma unroll
        for (int g = 0; g < 4; ++g) {
            accM[r][g][0] = bias2[g][0];
            accM[r][g][1] = bias2[g][1];
            accM[r][g][2] = bias2[g][0];
            accM[r][g][3] = bias2[g][1];
        }

    float hv0[4], hv1[4];

    // MUFU head start: act slice 0 first, while frag LDS is in flight
    act_r(accA[0], cst[0], hv0);
    frag_mma(accM[0], Xm + 0,   lane, bfr, 0);
    frag_mma(accM[1], Xm + 128, lane, bfr, 0);
    frag_mma(accM[0], Xm + 256, lane, bfr, 1);
    frag_mma(accM[1], Xm + 384, lane, bfr, 1);
    act_r(accA[1], cst[1], hv1);
    frag_mma(accM[0], Hm + 0,   lane, bfr, 2);
    frag_mma(accM[1], Hm + 128, lane, bfr, 2);
    frag_mma(accM[0], Hm + 256, lane, bfr, 3);
    frag_mma(accM[1], Hm + 384, lane, bfr, 3);

    // stage x(GA, t+1) + prefetch x(GA, t+2)
    {
        uint32_t* Xa = Xs + GA * 512;
        Xa[xoff0] = packh2(xr.x, xr.y);
        Xa[xoff1] = packh2(xr.z, xr.w);
        int tt = (t + 2 < T_LEN) ? t + 2 : T_LEN - 1;
        xr = *reinterpret_cast<const float4*>(xga + (size_t)tt * I_SZ);
    }

    frag_mma(accM[0], Hm + 512, lane, bfr, 4);
    frag_mma(accM[1], Hm + 640, lane, bfr, 4);

    // h(GA) writeback: 2 x STS.64 into frag-major H tile
    {
        uint32_t* Ha = Hs + GA * 1024;
        *reinterpret_cast<uint2*>(Ha + hoff0) =
            make_uint2(packh2(hv0[0], hv0[1]), packh2(hv0[2], hv0[3]));
        *reinterpret_cast<uint2*>(Ha + hoff1) =
            make_uint2(packh2(hv1[0], hv1[1]), packh2(hv1[2], hv1[3]));
    }

    frag_mma(accM[0], Hm + 768, lane, bfr, 5);
    frag_mma(accM[1], Hm + 896, lane, bfr, 5);
}

__global__ __launch_bounds__(NTHREADS, 1)
void lstm_fp16_kernel(const float* __restrict__ x,
                      const float* __restrict__ W_ih,
                      const float* __restrict__ W_hh,
                      const float* __restrict__ b_ih,
                      const float* __restrict__ b_hh,
                      const float* __restrict__ W_fc,
                      const float* __restrict__ b_fc,
                      float* __restrict__ out) {
    __shared__ __align__(16) uint32_t Xs[2 * 512];
    __shared__ __align__(16) uint32_t Hs[2 * 1024];

    const int tid  = threadIdx.x;
    const int warp = tid >> 5;
    const int lane = tid & 31;
    const int row0 = blockIdx.x * M_BLK;
    const int colw = warp * 8;
    const int arl  = lane >> 2;
    const int akl  = lane & 3;

    // ---- B fragments (fp16 half2), i/f/o pre-scaled by 0.5 ----
    uint32_t bfr[4][6][2];
    float bias2[4][2];
    {
        const int gc_base = colw + arl;
        #pragma unroll
        for (int g = 0; g < 4; ++g) {
            const int gc = g * 64 + gc_base;
            const float s = (g == 2) ? 1.0f : 0.5f;
            #pragma unroll
            for (int q = 0; q < 6; ++q) {
                const int k0 = q * 16 + 2 * akl;
                float w[4];
                #pragma unroll
                for (int j = 0; j < 4; ++j) {
                    const int k = k0 + ((j < 2) ? j : j + 6);   // k0,k0+1,k0+8,k0+9
                    w[j] = (k < I_SZ) ? W_ih[gc * I_SZ + k] : W_hh[gc * H_SZ + (k - I_SZ)];
                }
                bfr[g][q][0] = packh2(w[0] * s, w[1] * s);
                bfr[g][q][1] = packh2(w[2] * s, w[3] * s);
            }
            const int c0 = g * 64 + colw + 2 * akl;
            bias2[g][0] = (b_ih[c0] + b_hh[c0]) * s;
            bias2[g][1] = (b_ih[c0 + 1] + b_hh[c0 + 1]) * s;
        }
    }

    // zero H tiles (h0 = 0)
    for (int i = tid; i < 2 * 1024; i += NTHREADS) Hs[i] = 0u;

    // ---- x staging ownership: float4 per thread per group ----
    const int srow = tid >> 3;
    const int scol = (tid & 7) * 4;
    int xoff0, xoff1;
    {
        const int qx = scol >> 4, rx = srow >> 4;
        const int arls = srow & 7, subx = (srow >> 3) & 1;
        const int p0 = (scol & 15) >> 1;
        const int tg0 = p0 & 3, hfx = p0 >> 2;
        const int word = subx + 2 * hfx;
        xoff0 = (qx * 2 + rx) * 128 + (arls * 4 + tg0) * 4 + word;
        xoff1 = xoff0 + 4;
    }
    const int hoff0 = ((warp >> 1) * 2) * 128 + lane * 4 + 2 * (warp & 1);
    const int hoff1 = hoff0 + 128;

    const float* xga0 = x + ((size_t)(row0 + srow) * T_LEN) * I_SZ + scol;
    const float* xga1 = x + ((size_t)(row0 + 32 + srow) * T_LEN) * I_SZ + scol;

    float4 xr0, xr1;
    {
        float4 v0 = *reinterpret_cast<const float4*>(xga0);
        float4 v1 = *reinterpret_cast<const float4*>(xga1);
        Xs[xoff0]       = packh2(v0.x, v0.y);
        Xs[xoff1]       = packh2(v0.z, v0.w);
        Xs[512 + xoff0] = packh2(v1.x, v1.y);
        Xs[512 + xoff1] = packh2(v1.z, v1.w);
        xr0 = *reinterpret_cast<const float4*>(xga0 + I_SZ);
        xr1 = *reinterpret_cast<const float4*>(xga1 + I_SZ);
    }

    float acc0[2][4][4], acc1[2][4][4];
    float cst0[2][4] = {}, cst1[2][4] = {};

    __syncthreads();

    // prologue: gates(G0, 0) -> acc0
    {
        #pragma unroll
        for (int r = 0; r < 2; ++r)
            #pragma unroll
            for (int g = 0; g < 4; ++g) {
                acc0[r][g][0] = bias2[g][0];
                acc0[r][g][1] = bias2[g][1];
                acc0[r][g][2] = bias2[g][0];
                acc0[r][g][3] = bias2[g][1];
            }
        #pragma unroll
        for (int q = 0; q < 2; ++q)
            #pragma unroll
            for (int r = 0; r < 2; ++r)
                frag_mma(acc0[r], Xs + (q * 2 + r) * 128, lane, bfr, q);
        #pragma unroll
        for (int qh = 0; qh < 4; ++qh)
            #pragma unroll
            for (int r = 0; r < 2; ++r)
                frag_mma(acc0[r], Hs + (qh * 2 + r) * 128, lane, bfr, 2 + qh);
    }
    __syncthreads();

    for (int t = 0; t < T_LEN; ++t) {
        phase_fn<1, 0>(Xs, Hs, acc1, acc0, cst0, xr0, xga0, t, lane,
                       xoff0, xoff1, hoff0, hoff1, bfr, bias2);
        __syncthreads();
        phase_fn<0, 1>(Xs, Hs, acc0, acc1, cst1, xr1, xga1, t, lane,
                       xoff0, xoff1, hoff0, hoff1, bfr, bias2);
        __syncthreads();
    }

    // ---- FC epilogue: gather h_T from frag-major fp16 tiles ----
    for (int idx = tid; idx < M_BLK * OUT_SZ; idx += NTHREADS) {
        const int row = idx >> 3;
        const int o   = idx & 7;
        const int g   = row >> 5;
        const int lr  = row & 31;
        const int r   = lr >> 4, arle = lr & 7, sube = (lr >> 3) & 1;
        const uint32_t* Hg = Hs + g * 1024;
        const float* wf = W_fc + o * H_SZ;
        float s = b_fc[o];
        #pragma unroll
        for (int cc = 0; cc < 32; ++cc) {
            const int c  = cc * 2;
            const int qh = c >> 4;
            const int p  = (c & 15) >> 1;
            uint32_t wv = Hg[(qh * 2 + r) * 128 + (arle * 4 + (p & 3)) * 4 + sube + 2 * (p >> 2)];
            __half2 h2 = *reinterpret_cast<__half2*>(&wv);
            float2 f2 = __half22float2(h2);
            s += f2.x * wf[c] + f2.y * wf[c + 1];
        }
        out[(size_t)(row0 + row) * OUT_SZ + o] = s;
    }
}

extern "C" void kernel_launch(void* const* d_in, const int* in_sizes, int n_in,
                              void* d_out, int out_size) {
    const float* x    = (const float*)d_in[0];
    const float* W_ih = (const float*)d_in[1];
    const float* W_hh = (const float*)d_in[2];
    const float* b_ih = (const float*)d_in[3];
    const float* b_hh = (const float*)d_in[4];
    const float* W_fc = (const float*)d_in[5];
    const float* b_fc = (const float*)d_in[6];
    float* out = (float*)d_out;

    lstm_fp16_kernel<<<B_TOT / M_BLK, NTHREADS>>>(x, W_ih, W_hh, b_ih, b_hh, W_fc, b_fc, out);
}

// round 10
// speedup vs baseline: 1.0498x; 1.0498x over previous
#include <cuda_runtime.h>
#include <cuda_fp16.h>
#include <cstdint>

// LSTM B=8192, T=128, I=32, H=64, OUT=8.
// R9 = R7 (fp16 m16n8k16, frag-major LDS.128, 2-group interleaved pipeline,
// fp32 tanh.approx) + front-batched A-fragment loads: all 12 LDS.128 issued
// back-to-back at phase start (MLP=12), then a pure HMMA stream with MUFU
// act blocks as filler.

#define B_TOT 8192
#define T_LEN 128
#define I_SZ  32
#define H_SZ  64
#define OUT_SZ 8
#define M_BLK 64
#define NTHREADS 256

__device__ __forceinline__ uint32_t packh2(float a, float b) {
    __half2 h = __floats2half2_rn(a, b);
    return *reinterpret_cast<uint32_t*>(&h);
}
__device__ __forceinline__ float tanhhw(float x) {
    float y;
    asm("tanh.approx.f32 %0, %1;" : "=f"(y) : "f"(x));
    return y;
}
__device__ __forceinline__ void mma_f16(float c[4],
                                        uint32_t a0, uint32_t a1, uint32_t a2, uint32_t a3,
                                        uint32_t b0, uint32_t b1) {
    asm("mma.sync.aligned.m16n8k16.row.col.f32.f16.f16.f32 "
        "{%0,%1,%2,%3},{%4,%5,%6,%7},{%8,%9},{%0,%1,%2,%3};"
        : "+f"(c[0]), "+f"(c[1]), "+f"(c[2]), "+f"(c[3])
        : "r"(a0), "r"(a1), "r"(a2), "r"(a3), "r"(b0), "r"(b1));
}

// 4 gate MMAs on a preloaded A fragment
__device__ __forceinline__ void frag4(float accr[4][4], uint4 av,
                                      const uint32_t (&bfr)[4][6][2], int q) {
    #pragma unroll
    for (int g = 0; g < 4; ++g)
        mma_f16(accr[g], av.x, av.y, av.z, av.w, bfr[g][q][0], bfr[g][q][1]);
}

// activate 4 elems; i/f/o accs pre-scaled by 0.5 (sigmoid = 0.5*tanh+0.5)
__device__ __forceinline__ void act_r(const float acc[4][4], float cst[4], float hv[4]) {
    #pragma unroll
    for (int e = 0; e < 4; ++e) {
        float ig = fmaf(tanhhw(acc[0][e]), 0.5f, 0.5f);
        float fg = fmaf(tanhhw(acc[1][e]), 0.5f, 0.5f);
        float gg = tanhhw(acc[2][e]);
        float og = fmaf(tanhhw(acc[3][e]), 0.5f, 0.5f);
        float c  = fg * cst[e] + ig * gg;
        cst[e] = c;
        hv[e] = og * tanhhw(c);
    }
}

// Phase: mma(group GM) into accM; act(accA -> h of group GA); stage x(GA,t+1).
template <int GM, int GA>
__device__ __forceinline__ void phase_fn(uint32_t* __restrict__ Xs, uint32_t* __restrict__ Hs,
                                         float (&accM)[2][4][4], float (&accA)[2][4][4],
                                         float (&cst)[2][4], float4& xr,
                                         const float* __restrict__ xga, int t, int lane,
                                         int xoff0, int xoff1, int hoff0, int hoff1,
                                         const uint32_t (&bfr)[4][6][2],
                                         const float (&bias2)[4][2]) {
    const uint32_t* Xm = Xs + GM * 512;
    const uint32_t* Hm = Hs + GM * 1024;

    // ---- front-batch all 12 A-fragment LDS.128 (independent, MLP=12) ----
    uint4 av[12];
    #pragma unroll
    for (int b = 0; b < 4; ++b)
        av[b] = *reinterpret_cast<const uint4*>(Xm + b * 128 + lane * 4);
    #pragma unroll
    for (int b = 0; b < 8; ++b)
        av[4 + b] = *reinterpret_cast<const uint4*>(Hm + b * 128 + lane * 4);

    #pragma unroll
    for (int r = 0; r < 2; ++r)
        #pragma unroll
        for (int g = 0; g < 4; ++g) {
            accM[r][g][0] = bias2[g][0];
            accM[r][g][1] = bias2[g][1];
            accM[r][g][2] = bias2[g][0];
            accM[r][g][3] = bias2[g][1];
        }

    float hv0[4], hv1[4];

    // MUFU filler while LDS returns are in flight
    act_r(accA[0], cst[0], hv0);

    // x-part: q=0..1, blocks av[q*2+r]
    frag4(accM[0], av[0], bfr, 0);
    frag4(accM[1], av[1], bfr, 0);
    frag4(accM[0], av[2], bfr, 1);
    frag4(accM[1], av[3], bfr, 1);

    act_r(accA[1], cst[1], hv1);

    // h-part: q=2..5, blocks av[4 + (q-2)*2 + r]
    frag4(accM[0], av[4],  bfr, 2);
    frag4(accM[1], av[5],  bfr, 2);
    frag4(accM[0], av[6],  bfr, 3);
    frag4(accM[1], av[7],  bfr, 3);

    // stage x(GA, t+1) + prefetch x(GA, t+2)
    {
        uint32_t* Xa = Xs + GA * 512;
        Xa[xoff0] = packh2(xr.x, xr.y);
        Xa[xoff1] = packh2(xr.z, xr.w);
        int tt = (t + 2 < T_LEN) ? t + 2 : T_LEN - 1;
        xr = *reinterpret_cast<const float4*>(xga + (size_t)tt * I_SZ);
    }

    frag4(accM[0], av[8],  bfr, 4);
    frag4(accM[1], av[9],  bfr, 4);

    // h(GA) writeback: 2 x STS.64 into frag-major H tile
    {
        uint32_t* Ha = Hs + GA * 1024;
        *reinterpret_cast<uint2*>(Ha + hoff0) =
            make_uint2(packh2(hv0[0], hv0[1]), packh2(hv0[2], hv0[3]));
        *reinterpret_cast<uint2*>(Ha + hoff1) =
            make_uint2(packh2(hv1[0], hv1[1]), packh2(hv1[2], hv1[3]));
    }

    frag4(accM[0], av[10], bfr, 5);
    frag4(accM[1], av[11], bfr, 5);
}

__global__ __launch_bounds__(NTHREADS, 1)
void lstm_fp16_kernel(const float* __restrict__ x,
                      const float* __restrict__ W_ih,
                      const float* __restrict__ W_hh,
                      const float* __restrict__ b_ih,
                      const float* __restrict__ b_hh,
                      const float* __restrict__ W_fc,
                      const float* __restrict__ b_fc,
                      float* __restrict__ out) {
    __shared__ __align__(16) uint32_t Xs[2 * 512];
    __shared__ __align__(16) uint32_t Hs[2 * 1024];

    const int tid  = threadIdx.x;
    const int warp = tid >> 5;
    const int lane = tid & 31;
    const int row0 = blockIdx.x * M_BLK;
    const int colw = warp * 8;
    const int arl  = lane >> 2;
    const int akl  = lane & 3;

    // ---- B fragments (fp16 half2), i/f/o pre-scaled by 0.5 ----
    uint32_t bfr[4][6][2];
    float bias2[4][2];
    {
        const int gc_base = colw + arl;
        #pragma unroll
        for (int g = 0; g < 4; ++g) {
            const int gc = g * 64 + gc_base;
            const float s = (g == 2) ? 1.0f : 0.5f;
            #pragma unroll
            for (int q = 0; q < 6; ++q) {
                const int k0 = q * 16 + 2 * akl;
                float w[4];
                #pragma unroll
                for (int j = 0; j < 4; ++j) {
                    const int k = k0 + ((j < 2) ? j : j + 6);   // k0,k0+1,k0+8,k0+9
                    w[j] = (k < I_SZ) ? W_ih[gc * I_SZ + k] : W_hh[gc * H_SZ + (k - I_SZ)];
                }
                bfr[g][q][0] = packh2(w[0] * s, w[1] * s);
                bfr[g][q][1] = packh2(w[2] * s, w[3] * s);
            }
            const int c0 = g * 64 + colw + 2 * akl;
            bias2[g][0] = (b_ih[c0] + b_hh[c0]) * s;
            bias2[g][1] = (b_ih[c0 + 1] + b_hh[c0 + 1]) * s;
        }
    }

    // zero H tiles (h0 = 0)
    for (int i = tid; i < 2 * 1024; i += NTHREADS) Hs[i] = 0u;

    // ---- x staging ownership: float4 per thread per group ----
    const int srow = tid >> 3;
    const int scol = (tid & 7) * 4;
    int xoff0, xoff1;
    {
        const int qx = scol >> 4, rx = srow >> 4;
        const int arls = srow & 7, subx = (srow >> 3) & 1;
        const int p0 = (scol & 15) >> 1;
        const int tg0 = p0 & 3, hfx = p0 >> 2;
        const int word = subx + 2 * hfx;
        xoff0 = (qx * 2 + rx) * 128 + (arls * 4 + tg0) * 4 + word;
        xoff1 = xoff0 + 4;
    }
    const int hoff0 = ((warp >> 1) * 2) * 128 + lane * 4 + 2 * (warp & 1);
    const int hoff1 = hoff0 + 128;

    const float* xga0 = x + ((size_t)(row0 + srow) * T_LEN) * I_SZ + scol;
    const float* xga1 = x + ((size_t)(row0 + 32 + srow) * T_LEN) * I_SZ + scol;

    float4 xr0, xr1;
    {
        float4 v0 = *reinterpret_cast<const float4*>(xga0);
        float4 v1 = *reinterpret_cast<const float4*>(xga1);
        Xs[xoff0]       = packh2(v0.x, v0.y);
        Xs[xoff1]       = packh2(v0.z, v0.w);
        Xs[512 + xoff0] = packh2(v1.x, v1.y);
        Xs[512 + xoff1] = packh2(v1.z, v1.w);
        xr0 = *reinterpret_cast<const float4*>(xga0 + I_SZ);
        xr1 = *reinterpret_cast<const float4*>(xga1 + I_SZ);
    }

    float acc0[2][4][4], acc1[2][4][4];
    float cst0[2][4] = {}, cst1[2][4] = {};

    __syncthreads();

    // prologue: gates(G0, 0) -> acc0
    {
        #pragma unroll
        for (int r = 0; r < 2; ++r)
            #pragma unroll
            for (int g = 0; g < 4; ++g) {
                acc0[r][g][0] = bias2[g][0];
                acc0[r][g][1] = bias2[g][1];
                acc0[r][g][2] = bias2[g][0];
                acc0[r][g][3] = bias2[g][1];
            }
        #pragma unroll
        for (int q = 0; q < 2; ++q)
            #pragma unroll
            for (int r = 0; r < 2; ++r) {
                uint4 av = *reinterpret_cast<const uint4*>(Xs + (q * 2 + r) * 128 + lane * 4);
                frag4(acc0[r], av, bfr, q);
            }
        #pragma unroll
        for (int qh = 0; qh < 4; ++qh)
            #pragma unroll
            for (int r = 0; r < 2; ++r) {
                uint4 av = *reinterpret_cast<const uint4*>(Hs + (qh * 2 + r) * 128 + lane * 4);
                frag4(acc0[r], av, bfr, 2 + qh);
            }
    }
    __syncthreads();

    for (int t = 0; t < T_LEN; ++t) {
        phase_fn<1, 0>(Xs, Hs, acc1, acc0, cst0, xr0, xga0, t, lane,
                       xoff0, xoff1, hoff0, hoff1, bfr, bias2);
        __syncthreads();
        phase_fn<0, 1>(Xs, Hs, acc0, acc1, cst1, xr1, xga1, t, lane,
                       xoff0, xoff1, hoff0, hoff1, bfr, bias2);
        __syncthreads();
    }

    // ---- FC epilogue: gather h_T from frag-major fp16 tiles ----
    for (int idx = tid; idx < M_BLK * OUT_SZ; idx += NTHREADS) {
        const int row = idx >> 3;
        const int o   = idx & 7;
        const int g   = row >> 5;
        const int lr  = row & 31;
        const int r   = lr >> 4, arle = lr & 7, sube = (lr >> 3) & 1;
        const uint32_t* Hg = Hs + g * 1024;
        const float* wf = W_fc + o * H_SZ;
        float s = b_fc[o];
        #pragma unroll
        for (int cc = 0; cc < 32; ++cc) {
            const int c  = cc * 2;
            const int qh = c >> 4;
            const int p  = (c & 15) >> 1;
            uint32_t wv = Hg[(qh * 2 + r) * 128 + (arle * 4 + (p & 3)) * 4 + sube + 2 * (p >> 2)];
            __half2 h2 = *reinterpret_cast<__half2*>(&wv);
            float2 f2 = __half22float2(h2);
            s += f2.x * wf[c] + f2.y * wf[c + 1];
        }
        out[(size_t)(row0 + row) * OUT_SZ + o] = s;
    }
}

extern "C" void kernel_launch(void* const* d_in, const int* in_sizes, int n_in,
                              void* d_out, int out_size) {
    const float* x    = (const float*)d_in[0];
    const float* W_ih = (const float*)d_in[1];
    const float* W_hh = (const float*)d_in[2];
    const float* b_ih = (const float*)d_in[3];
    const float* b_hh = (const float*)d_in[4];
    const float* W_fc = (const float*)d_in[5];
    const float* b_fc = (const float*)d_in[6];
    float* out = (float*)d_out;

    lstm_fp16_kernel<<<B_TOT / M_BLK, NTHREADS>>>(x, W_ih, W_hh, b_ih, b_hh, W_fc, b_fc, out);
}